// round 3
// baseline (speedup 1.0000x reference)
#include <cuda_runtime.h>
#include <math.h>

#define T_ 2048
#define H_ 1024
#define E_ 8
#define F_ 2048
#define KSEL 2
#define MAXROWS 5120   // 4096 assignments + 8 experts * 127 padding worst case, 128-aligned

// ---------------- device scratch (no allocations allowed) ----------------
__device__ __align__(16) float g_act[(size_t)MAXROWS * F_];   // silu(X@w1) rows
__device__ __align__(16) float g_y[(size_t)MAXROWS * H_];     // expert outputs per slot
__device__ int   g_row_token[MAXROWS];
__device__ float g_row_weight[MAXROWS];
__device__ int   g_token_slot[T_ * KSEL];
__device__ int   g_te[T_ * KSEL];
__device__ float g_tw[T_ * KSEL];
__device__ int   g_count[E_];
__device__ int   g_off[E_ + 1];
__device__ int   g_cursor[E_];
__device__ float g_probsum[E_];
__device__ float g_lse2;
__device__ int   g_total;

// ---------------- init: reset all per-launch state ----------------
__global__ void zero_kernel() {
    int i = blockIdx.x * blockDim.x + threadIdx.x;
    if (i < MAXROWS) { g_row_token[i] = -1; g_row_weight[i] = 0.f; }
    if (i < E_) { g_count[i] = 0; g_probsum[i] = 0.f; g_cursor[i] = 0; }
    if (i == 0) { g_lse2 = 0.f; }
}

// ---------------- router: one warp per token ----------------
__global__ void router_kernel(const float* __restrict__ hidden,
                              const float* __restrict__ rw) {
    int warp = (blockIdx.x * blockDim.x + threadIdx.x) >> 5;
    int lane = threadIdx.x & 31;
    if (warp >= T_) return;
    int t = warp;

    const float4* h4  = (const float4*)(hidden + (size_t)t * H_);
    const float4* rw4 = (const float4*)rw;   // rw is [H][E] row-major, 8 floats/row

    float acc[E_];
#pragma unroll
    for (int e = 0; e < E_; e++) acc[e] = 0.f;

#pragma unroll
    for (int i = 0; i < 8; i++) {           // 256 float4 per row / 32 lanes
        int idx = i * 32 + lane;
        float4 x = h4[idx];
        int hb = idx * 4;
        float xv[4] = {x.x, x.y, x.z, x.w};
#pragma unroll
        for (int j = 0; j < 4; j++) {
            float4 r0 = rw4[(hb + j) * 2 + 0];
            float4 r1 = rw4[(hb + j) * 2 + 1];
            acc[0] += xv[j] * r0.x; acc[1] += xv[j] * r0.y;
            acc[2] += xv[j] * r0.z; acc[3] += xv[j] * r0.w;
            acc[4] += xv[j] * r1.x; acc[5] += xv[j] * r1.y;
            acc[6] += xv[j] * r1.z; acc[7] += xv[j] * r1.w;
        }
    }
#pragma unroll
    for (int off = 16; off > 0; off >>= 1)
#pragma unroll
        for (int e = 0; e < E_; e++)
            acc[e] += __shfl_xor_sync(0xFFFFFFFFu, acc[e], off);

    if (lane == 0) {
        float mx = acc[0];
#pragma unroll
        for (int e = 1; e < E_; e++) mx = fmaxf(mx, acc[e]);
        float p[E_], s = 0.f;
#pragma unroll
        for (int e = 0; e < E_; e++) { p[e] = expf(acc[e] - mx); s += p[e]; }
        float inv = 1.f / s;
#pragma unroll
        for (int e = 0; e < E_; e++) p[e] *= inv;
        float lse = logf(s) + mx;
        atomicAdd(&g_lse2, lse * lse);
#pragma unroll
        for (int e = 0; e < E_; e++) atomicAdd(&g_probsum[e], p[e]);

        // top-2, ties -> lowest index first (jax top_k semantics)
        int i0 = 0;
#pragma unroll
        for (int e = 1; e < E_; e++) if (p[e] > p[i0]) i0 = e;
        int i1 = (i0 == 0) ? 1 : 0;
#pragma unroll
        for (int e = 0; e < E_; e++) if (e != i0 && p[e] > p[i1]) i1 = e;

        float s2 = p[i0] + p[i1];
        float w0 = p[i0] / s2, w1 = p[i1] / s2;
        g_te[2 * t + 0] = i0; g_te[2 * t + 1] = i1;
        g_tw[2 * t + 0] = w0; g_tw[2 * t + 1] = w1;
        atomicAdd(&g_count[i0], 1);
        atomicAdd(&g_count[i1], 1);
    }
}

// ---------------- offsets: 128-aligned segment starts ----------------
__global__ void offsets_kernel() {
    if (threadIdx.x == 0 && blockIdx.x == 0) {
        int o = 0;
        g_off[0] = 0;
        for (int e = 0; e < E_; e++) {
            g_cursor[e] = o;
            o += ((g_count[e] + 127) >> 7) << 7;
            g_off[e + 1] = o;
        }
        g_total = o;
    }
}

// ---------------- scatter tokens into expert-sorted slots ----------------
__global__ void scatter_kernel() {
    int t = blockIdx.x * blockDim.x + threadIdx.x;
    if (t >= T_) return;
#pragma unroll
    for (int k = 0; k < KSEL; k++) {
        int e = g_te[2 * t + k];
        int slot = atomicAdd(&g_cursor[e], 1);
        g_row_token[slot]  = t;
        g_row_weight[slot] = g_tw[2 * t + k];
        g_token_slot[2 * t + k] = slot;
    }
}

// ---------------- grouped GEMM: 128x128 tile, 8x8 microtile, BK=8 ----------------
// Double-buffered smem: one __syncthreads per K-iteration.
// MODE 1: act = silu(gather(hidden) @ w1[e])   (N=F, K=H)
// MODE 2: y   = act @ w2[e]                    (N=H, K=F)
template <int MODE>
__global__ __launch_bounds__(256, 2) void gemm_kernel(const float* __restrict__ X,
                                                      const float* __restrict__ W) {
    constexpr int N  = (MODE == 1) ? F_ : H_;
    constexpr int KD = (MODE == 1) ? H_ : F_;

    const int row0 = blockIdx.y * 128;
    if (row0 >= g_total) return;

    int e = 0;
#pragma unroll
    for (int i = 0; i < E_; i++) if (row0 >= g_off[i + 1]) e++;
    const float* B = W + (size_t)e * KD * N;
    const int n0 = blockIdx.x * 128;

    __shared__ float As[2][8][128];
    __shared__ float Bs[2][8][128];

    const int tid = threadIdx.x;
    const int a_m = tid >> 1, a_k = (tid & 1) * 4;
    const int b_k = tid >> 5, b_n = (tid & 31) * 4;
    const int mb = (tid >> 4) * 8, nb = (tid & 15) * 8;

    const float* Arow;
    if (MODE == 1) {
        int tok = g_row_token[row0 + a_m];
        Arow = (tok >= 0) ? (X + (size_t)tok * H_ + a_k) : nullptr;
    } else {
        Arow = g_act + (size_t)(row0 + a_m) * F_ + a_k;
    }
    const float* Bptr = B + (size_t)b_k * N + n0 + b_n;

    float acc[8][8];
#pragma unroll
    for (int i = 0; i < 8; i++)
#pragma unroll
        for (int j = 0; j < 8; j++) acc[i][j] = 0.f;

    float4 av = Arow ? *(const float4*)(Arow) : make_float4(0.f, 0.f, 0.f, 0.f);
    float4 bv = *(const float4*)(Bptr);

    int buf = 0;
    As[0][a_k + 0][a_m] = av.x;
    As[0][a_k + 1][a_m] = av.y;
    As[0][a_k + 2][a_m] = av.z;
    As[0][a_k + 3][a_m] = av.w;
    *(float4*)&Bs[0][b_k][b_n] = bv;
    __syncthreads();

    int k0 = 0;
    while (true) {
        int kn = k0 + 8;
        if (kn < KD) {   // register-prefetch next tiles during compute
            av = Arow ? *(const float4*)(Arow + kn) : make_float4(0.f, 0.f, 0.f, 0.f);
            bv = *(const float4*)(Bptr + (size_t)kn * N);
        }

#pragma unroll
        for (int kk = 0; kk < 8; kk++) {
            float a8[8], b8[8];
            *(float4*)&a8[0] = *(const float4*)&As[buf][kk][mb];
            *(float4*)&a8[4] = *(const float4*)&As[buf][kk][mb + 4];
            *(float4*)&b8[0] = *(const float4*)&Bs[buf][kk][nb];
            *(float4*)&b8[4] = *(const float4*)&Bs[buf][kk][nb + 4];
#pragma unroll
            for (int i = 0; i < 8; i++)
#pragma unroll
                for (int j = 0; j < 8; j++)
                    acc[i][j] += a8[i] * b8[j];
        }

        if (kn >= KD) break;

        // write next stage into the other buffer; single barrier publishes it
        buf ^= 1;
        As[buf][a_k + 0][a_m] = av.x;
        As[buf][a_k + 1][a_m] = av.y;
        As[buf][a_k + 2][a_m] = av.z;
        As[buf][a_k + 3][a_m] = av.w;
        *(float4*)&Bs[buf][b_k][b_n] = bv;
        k0 = kn;
        __syncthreads();
    }

    float* C = (MODE == 1) ? g_act : g_y;
#pragma unroll
    for (int i = 0; i < 8; i++) {
        float v[8];
#pragma unroll
        for (int j = 0; j < 8; j++) {
            float x = acc[i][j];
            if (MODE == 1) x = x / (1.f + expf(-x));   // silu
            v[j] = x;
        }
        float* crow = C + (size_t)(row0 + mb + i) * N + n0 + nb;
        *(float4*)&crow[0] = *(float4*)&v[0];
        *(float4*)&crow[4] = *(float4*)&v[4];
    }
}

// ---------------- combine: out[t] = w0*y[s0] + w1*y[s1] ----------------
__global__ void combine_kernel(float* __restrict__ out) {
    int idx = blockIdx.x * blockDim.x + threadIdx.x;   // over T*H/4 float4s
    int t = idx >> 8;          // 256 float4 per row
    int c = idx & 255;
    int s0 = g_token_slot[2 * t], s1 = g_token_slot[2 * t + 1];
    float w0 = g_row_weight[s0], w1 = g_row_weight[s1];
    float4 a = ((const float4*)(g_y + (size_t)s0 * H_))[c];
    float4 b = ((const float4*)(g_y + (size_t)s1 * H_))[c];
    float4 r;
    r.x = w0 * a.x + w1 * b.x;
    r.y = w0 * a.y + w1 * b.y;
    r.z = w0 * a.z + w1 * b.z;
    r.w = w0 * a.w + w1 * b.w;
    ((float4*)out)[idx] = r;
}

// ---------------- finalize: the two loss scalars ----------------
__global__ void finalize_kernel(float* __restrict__ out) {
    if (threadIdx.x == 0 && blockIdx.x == 0) {
        float s = 0.f;
#pragma unroll
        for (int e = 0; e < E_; e++) s += (float)g_count[e] * g_probsum[e];
        out[(size_t)T_ * H_ + 0] = 0.01f * (float)E_ * s / ((float)T_ * (float)T_);
        out[(size_t)T_ * H_ + 1] = 0.001f * g_lse2 / (float)T_;
    }
}

// ---------------- launch ----------------
extern "C" void kernel_launch(void* const* d_in, const int* in_sizes, int n_in,
                              void* d_out, int out_size) {
    const float* hidden = (const float*)d_in[0];
    const float* rw     = (const float*)d_in[1];
    const float* w1     = (const float*)d_in[2];
    const float* w2     = (const float*)d_in[3];
    float* out = (float*)d_out;

    zero_kernel<<<(MAXROWS + 255) / 256, 256>>>();
    router_kernel<<<(T_ * 32 + 255) / 256, 256>>>(hidden, rw);
    offsets_kernel<<<1, 32>>>();
    scatter_kernel<<<(T_ + 255) / 256, 256>>>();
    // worst-case fixed grids (graph capture needs static launch config);
    // blocks beyond g_total early-exit.
    gemm_kernel<1><<<dim3(F_ / 128, MAXROWS / 128), 256>>>(hidden, w1);
    gemm_kernel<2><<<dim3(H_ / 128, MAXROWS / 128), 256>>>(nullptr, w2);
    combine_kernel<<<(T_ * H_ / 4) / 256, 256>>>(out);
    finalize_kernel<<<1, 32>>>(out);
}

// round 9
// speedup vs baseline: 2.0168x; 2.0168x over previous
#include <cuda_runtime.h>
#include <cuda_bf16.h>
#include <math.h>
#include <stdint.h>

#define T_ 2048
#define H_ 1024
#define E_ 8
#define F_ 2048
#define KSEL 2
#define MAXROWS 5120   // 4096 assignments + 8*127 padding worst case, 128-aligned

// ---------------- device scratch: keep total <= ~60 MiB (round-3-proven) ------
__device__ __align__(16) float g_act[(size_t)MAXROWS * F_];   // 40 MiB
__device__ __align__(16) float g_y[(size_t)MAXROWS * H_];     // 20 MiB
__device__ int   g_row_token[MAXROWS];
__device__ float g_row_weight[MAXROWS];
__device__ int   g_token_slot[T_ * KSEL];
__device__ int   g_te[T_ * KSEL];
__device__ float g_tw[T_ * KSEL];
__device__ int   g_count[E_];
__device__ int   g_off[E_ + 1];
__device__ int   g_cursor[E_];
__device__ float g_probsum[E_];
__device__ float g_lse2;
__device__ int   g_total;

// ---------------- PTX helpers (plain sm_100-legal only) ----------------
__device__ __forceinline__ uint32_t smem_u32(const void* p) {
    uint32_t a;
    asm("{ .reg .u64 t; cvta.to.shared.u64 t, %1; cvt.u32.u64 %0, t; }" : "=r"(a) : "l"(p));
    return a;
}
__device__ __forceinline__ void ldsm4(uint32_t& r0, uint32_t& r1, uint32_t& r2, uint32_t& r3,
                                      uint32_t addr) {
    asm volatile("ldmatrix.sync.aligned.m8n8.x4.shared.b16 {%0,%1,%2,%3}, [%4];"
                 : "=r"(r0), "=r"(r1), "=r"(r2), "=r"(r3) : "r"(addr));
}
__device__ __forceinline__ void ldsm4t(uint32_t& r0, uint32_t& r1, uint32_t& r2, uint32_t& r3,
                                       uint32_t addr) {
    asm volatile("ldmatrix.sync.aligned.m8n8.x4.trans.shared.b16 {%0,%1,%2,%3}, [%4];"
                 : "=r"(r0), "=r"(r1), "=r"(r2), "=r"(r3) : "r"(addr));
}
// scalar-ref form: no pointers cross the asm boundary
__device__ __forceinline__ void mma16816(float& d0, float& d1, float& d2, float& d3,
                                         uint32_t a0, uint32_t a1, uint32_t a2, uint32_t a3,
                                         uint32_t b0, uint32_t b1) {
    asm volatile(
        "mma.sync.aligned.m16n8k16.row.col.f32.bf16.bf16.f32 "
        "{%0,%1,%2,%3}, {%4,%5,%6,%7}, {%8,%9}, {%0,%1,%2,%3};"
        : "+f"(d0), "+f"(d1), "+f"(d2), "+f"(d3)
        : "r"(a0), "r"(a1), "r"(a2), "r"(a3), "r"(b0), "r"(b1));
}
__device__ __forceinline__ uint32_t pack2(__nv_bfloat16 a, __nv_bfloat16 b) {
    __nv_bfloat162 t; t.x = a; t.y = b;
    return *reinterpret_cast<uint32_t*>(&t);
}
__device__ __forceinline__ void split2(float x, float y, uint32_t& hi, uint32_t& lo) {
    __nv_bfloat16 hx = __float2bfloat16(x), hy = __float2bfloat16(y);
    hi = pack2(hx, hy);
    lo = pack2(__float2bfloat16(x - __bfloat162float(hx)),
               __float2bfloat16(y - __bfloat162float(hy)));
}

// ---------------- init ----------------
__global__ void zero_kernel() {
    int i = blockIdx.x * blockDim.x + threadIdx.x;
    if (i < MAXROWS) { g_row_token[i] = -1; g_row_weight[i] = 0.f; }
    if (i < E_) { g_count[i] = 0; g_probsum[i] = 0.f; g_cursor[i] = 0; }
    if (i == 0) { g_lse2 = 0.f; }
}

// ---------------- router: one warp per token ----------------
__global__ void router_kernel(const float* __restrict__ hidden,
                              const float* __restrict__ rw) {
    int warp = (blockIdx.x * blockDim.x + threadIdx.x) >> 5;
    int lane = threadIdx.x & 31;
    if (warp >= T_) return;
    int t = warp;
    const float4* h4  = (const float4*)(hidden + (size_t)t * H_);
    const float4* rw4 = (const float4*)rw;
    float acc[E_];
#pragma unroll
    for (int e = 0; e < E_; e++) acc[e] = 0.f;
#pragma unroll
    for (int i = 0; i < 8; i++) {
        int idx = i * 32 + lane;
        float4 x = h4[idx];
        int hb = idx * 4;
        float xv[4] = {x.x, x.y, x.z, x.w};
#pragma unroll
        for (int j = 0; j < 4; j++) {
            float4 r0 = rw4[(hb + j) * 2 + 0];
            float4 r1 = rw4[(hb + j) * 2 + 1];
            acc[0] += xv[j] * r0.x; acc[1] += xv[j] * r0.y;
            acc[2] += xv[j] * r0.z; acc[3] += xv[j] * r0.w;
            acc[4] += xv[j] * r1.x; acc[5] += xv[j] * r1.y;
            acc[6] += xv[j] * r1.z; acc[7] += xv[j] * r1.w;
        }
    }
#pragma unroll
    for (int off = 16; off > 0; off >>= 1)
#pragma unroll
        for (int e = 0; e < E_; e++)
            acc[e] += __shfl_xor_sync(0xFFFFFFFFu, acc[e], off);
    if (lane == 0) {
        float mx = acc[0];
#pragma unroll
        for (int e = 1; e < E_; e++) mx = fmaxf(mx, acc[e]);
        float p[E_], s = 0.f;
#pragma unroll
        for (int e = 0; e < E_; e++) { p[e] = expf(acc[e] - mx); s += p[e]; }
        float inv = 1.f / s;
#pragma unroll
        for (int e = 0; e < E_; e++) p[e] *= inv;
        float lse = logf(s) + mx;
        atomicAdd(&g_lse2, lse * lse);
#pragma unroll
        for (int e = 0; e < E_; e++) atomicAdd(&g_probsum[e], p[e]);

        // top-2 with value tracking (strict >, ties keep lowest index)
        float v0 = -1.f; int i0 = 0;
#pragma unroll
        for (int e = 0; e < E_; e++) if (p[e] > v0) { v0 = p[e]; i0 = e; }
        float v1 = -1.f; int i1 = 0;
#pragma unroll
        for (int e = 0; e < E_; e++) if (e != i0 && p[e] > v1) { v1 = p[e]; i1 = e; }

        float s2 = v0 + v1;
        g_te[2 * t + 0] = i0; g_te[2 * t + 1] = i1;
        g_tw[2 * t + 0] = v0 / s2; g_tw[2 * t + 1] = v1 / s2;
        atomicAdd(&g_count[i0], 1);
        atomicAdd(&g_count[i1], 1);
    }
}

// ---------------- offsets ----------------
__global__ void offsets_kernel() {
    if (threadIdx.x == 0 && blockIdx.x == 0) {
        int o = 0;
        g_off[0] = 0;
        for (int e = 0; e < E_; e++) {
            g_cursor[e] = o;
            o += ((g_count[e] + 127) >> 7) << 7;
            g_off[e + 1] = o;
        }
        g_total = o;
    }
}

// ---------------- scatter ----------------
__global__ void scatter_kernel() {
    int t = blockIdx.x * blockDim.x + threadIdx.x;
    if (t >= T_) return;
#pragma unroll
    for (int k = 0; k < KSEL; k++) {
        int e = g_te[2 * t + k];
        int slot = atomicAdd(&g_cursor[e], 1);
        g_row_token[slot]  = t;
        g_row_weight[slot] = g_tw[2 * t + k];
        g_token_slot[2 * t + k] = slot;
    }
}

// ---------------- grouped GEMM: mma.sync split-bf16x3, inline fp32->hi/lo ----
// tile 128x128, 8 warps (4M x 2N), BK=32, double-buffered smem, reg prefetch.
// A smem: [128 m][40 bf16] rows (80 B stride), hi+lo.
// B smem: [32 k][136 bf16] rows (272 B stride, K-major; ldmatrix.trans), hi+lo.
#define OFF_AHI 0
#define OFF_ALO 10240
#define OFF_BHI 20480
#define OFF_BLO 29184
#define BUF_B   37888
#define S_TOK   75776
#define SM_BYTES 76288

template <int MODE>
__global__ __launch_bounds__(256) void mma_gemm(const float* __restrict__ Xsrc,
                                                const float* __restrict__ Wsrc) {
    constexpr int KD  = (MODE == 1) ? H_ : F_;   // contraction dim
    constexpr int NS  = (MODE == 1) ? F_ : H_;   // W row stride (= N total)
    constexpr int NST = KD / 32;

    const int row0 = blockIdx.y * 128;
    if (row0 >= g_total) return;
    const int n0 = blockIdx.x * 128;

    extern __shared__ char smem[];
    const uint32_t sb = smem_u32(smem);
    const int tid = threadIdx.x;
    const int wid = tid >> 5, lane = tid & 31;
    const int wm = wid & 3, wn = wid >> 2;       // warp grid 4x2

    int e = 0;
#pragma unroll
    for (int i = 0; i < E_; i++) if (row0 >= g_off[i + 1]) e++;
    const float* Wb = Wsrc + (size_t)e * KD * NS + n0;   // W[e][k][n0+..]

    int* s_tok = (int*)(smem + S_TOK);
    if (MODE == 1 && tid < 128) s_tok[tid] = g_row_token[row0 + tid];
    __syncthreads();

    // staging coords: A: r=lin>>3 (0..127), kq=lin&7; B: k=lin>>5 (0..31), nq=lin&31
    float4 pa[4], pb[4];

    auto LOAD = [&](int k0) {
#pragma unroll
        for (int it = 0; it < 4; it++) {
            int lin = it * 256 + tid; int r = lin >> 3; int kq = lin & 7;
            if (MODE == 1) {
                int tok = s_tok[r];
                pa[it] = (tok >= 0) ? *(const float4*)(Xsrc + (size_t)tok * H_ + k0 + kq * 4)
                                    : make_float4(0.f, 0.f, 0.f, 0.f);
            } else {
                pa[it] = *(const float4*)(g_act + (size_t)(row0 + r) * F_ + k0 + kq * 4);
            }
        }
#pragma unroll
        for (int it = 0; it < 4; it++) {
            int lin = it * 256 + tid; int k = lin >> 5; int nq = lin & 31;
            pb[it] = *(const float4*)(Wb + (size_t)(k0 + k) * NS + nq * 4);
        }
    };
    auto STORE = [&](int buf) {
        char* bp = smem + buf * BUF_B;
#pragma unroll
        for (int it = 0; it < 4; it++) {
            int lin = it * 256 + tid; int r = lin >> 3; int kq = lin & 7;
            uint32_t h0, h1, l0, l1;
            split2(pa[it].x, pa[it].y, h0, l0);
            split2(pa[it].z, pa[it].w, h1, l1);
            uint32_t off = r * 80 + kq * 8;
            *(uint2*)(bp + OFF_AHI + off) = make_uint2(h0, h1);
            *(uint2*)(bp + OFF_ALO + off) = make_uint2(l0, l1);
        }
#pragma unroll
        for (int it = 0; it < 4; it++) {
            int lin = it * 256 + tid; int k = lin >> 5; int nq = lin & 31;
            uint32_t h0, h1, l0, l1;
            split2(pb[it].x, pb[it].y, h0, l0);
            split2(pb[it].z, pb[it].w, h1, l1);
            uint32_t off = k * 272 + nq * 8;
            *(uint2*)(bp + OFF_BHI + off) = make_uint2(h0, h1);
            *(uint2*)(bp + OFF_BLO + off) = make_uint2(l0, l1);
        }
    };

    float acc[2][8][4];
#pragma unroll
    for (int i = 0; i < 2; i++)
#pragma unroll
        for (int j = 0; j < 8; j++)
#pragma unroll
            for (int q = 0; q < 4; q++) acc[i][j][q] = 0.f;

    LOAD(0);
    STORE(0);
    __syncthreads();

    for (int s = 0; s < NST; s++) {
        const int buf = s & 1;
        if (s + 1 < NST) LOAD((s + 1) * 32);

        const uint32_t bufb = sb + buf * BUF_B;
#pragma unroll
        for (int pass = 0; pass < 3; pass++) {
            const uint32_t abase = bufb + ((pass == 2) ? OFF_ALO : OFF_AHI);
            const uint32_t bbase = bufb + ((pass == 1) ? OFF_BLO : OFF_BHI);
#pragma unroll
            for (int ks = 0; ks < 2; ks++) {
                const int k16 = ks * 16;
                uint32_t a_r[2][4];
#pragma unroll
                for (int mi = 0; mi < 2; mi++) {
                    uint32_t addr = abase + (wm * 32 + mi * 16 + (lane & 15)) * 80
                                  + (k16 + (lane >> 4) * 8) * 2;
                    ldsm4(a_r[mi][0], a_r[mi][1], a_r[mi][2], a_r[mi][3], addr);
                }
                uint32_t b_r[4][4];
#pragma unroll
                for (int nj = 0; nj < 4; nj++) {
                    uint32_t addr = bbase
                                  + (k16 + ((lane >> 3) & 1) * 8 + (lane & 7)) * 272
                                  + (wn * 64 + nj * 16 + (lane >> 4) * 8) * 2;
                    ldsm4t(b_r[nj][0], b_r[nj][1], b_r[nj][2], b_r[nj][3], addr);
                }
#pragma unroll
                for (int mi = 0; mi < 2; mi++)
#pragma unroll
                    for (int nj = 0; nj < 4; nj++) {
                        mma16816(acc[mi][2 * nj + 0][0], acc[mi][2 * nj + 0][1],
                                 acc[mi][2 * nj + 0][2], acc[mi][2 * nj + 0][3],
                                 a_r[mi][0], a_r[mi][1], a_r[mi][2], a_r[mi][3],
                                 b_r[nj][0], b_r[nj][1]);
                        mma16816(acc[mi][2 * nj + 1][0], acc[mi][2 * nj + 1][1],
                                 acc[mi][2 * nj + 1][2], acc[mi][2 * nj + 1][3],
                                 a_r[mi][0], a_r[mi][1], a_r[mi][2], a_r[mi][3],
                                 b_r[nj][2], b_r[nj][3]);
                    }
            }
        }

        if (s + 1 < NST) {
            STORE(buf ^ 1);      // other buffer; everyone passed last sync, safe
            __syncthreads();
        }
    }

    // epilogue: frag (mi,ni): c0,c1 at (row tr, col tc), c2,c3 at (row tr+8)
    const int tr = lane >> 2, tc = (lane & 3) * 2;
    const int rbase = row0 + wm * 32 + tr;
    const int cbase = n0 + wn * 64 + tc;
#pragma unroll
    for (int mi = 0; mi < 2; mi++)
#pragma unroll
        for (int ni = 0; ni < 8; ni++) {
            const int r = rbase + mi * 16;
            const int c = cbase + ni * 8;
            float a0 = acc[mi][ni][0], a1 = acc[mi][ni][1];
            float a2 = acc[mi][ni][2], a3 = acc[mi][ni][3];
            if (MODE == 1) {
                float s0 = a0 / (1.f + expf(-a0));
                float s1 = a1 / (1.f + expf(-a1));
                float s2 = a2 / (1.f + expf(-a2));
                float s3 = a3 / (1.f + expf(-a3));
                *(float2*)(g_act + (size_t)r * F_ + c)       = make_float2(s0, s1);
                *(float2*)(g_act + (size_t)(r + 8) * F_ + c) = make_float2(s2, s3);
            } else {
                *(float2*)(g_y + (size_t)r * H_ + c)       = make_float2(a0, a1);
                *(float2*)(g_y + (size_t)(r + 8) * H_ + c) = make_float2(a2, a3);
            }
        }
}

// ---------------- combine ----------------
__global__ void combine_kernel(float* __restrict__ out) {
    int idx = blockIdx.x * blockDim.x + threadIdx.x;
    int t = idx >> 8, c = idx & 255;
    int s0 = g_token_slot[2 * t], s1 = g_token_slot[2 * t + 1];
    float w0 = g_row_weight[s0], w1 = g_row_weight[s1];
    float4 a = ((const float4*)(g_y + (size_t)s0 * H_))[c];
    float4 b = ((const float4*)(g_y + (size_t)s1 * H_))[c];
    float4 r;
    r.x = w0 * a.x + w1 * b.x;
    r.y = w0 * a.y + w1 * b.y;
    r.z = w0 * a.z + w1 * b.z;
    r.w = w0 * a.w + w1 * b.w;
    ((float4*)out)[idx] = r;
}

// ---------------- finalize ----------------
__global__ void finalize_kernel(float* __restrict__ out) {
    if (threadIdx.x == 0 && blockIdx.x == 0) {
        float s = 0.f;
#pragma unroll
        for (int e = 0; e < E_; e++) s += (float)g_count[e] * g_probsum[e];
        out[(size_t)T_ * H_ + 0] = 0.01f * (float)E_ * s / ((float)T_ * (float)T_);
        out[(size_t)T_ * H_ + 1] = 0.001f * g_lse2 / (float)T_;
    }
}

// ---------------- launch ----------------
extern "C" void kernel_launch(void* const* d_in, const int* in_sizes, int n_in,
                              void* d_out, int out_size) {
    const float* hidden = (const float*)d_in[0];
    const float* rw     = (const float*)d_in[1];
    const float* w1     = (const float*)d_in[2];
    const float* w2     = (const float*)d_in[3];
    float* out = (float*)d_out;

    cudaFuncSetAttribute(mma_gemm<1>, cudaFuncAttributeMaxDynamicSharedMemorySize, SM_BYTES);
    cudaFuncSetAttribute(mma_gemm<2>, cudaFuncAttributeMaxDynamicSharedMemorySize, SM_BYTES);

    zero_kernel<<<(MAXROWS + 255) / 256, 256>>>();
    router_kernel<<<(T_ * 32 + 255) / 256, 256>>>(hidden, rw);
    offsets_kernel<<<1, 32>>>();
    scatter_kernel<<<(T_ + 255) / 256, 256>>>();
    mma_gemm<1><<<dim3(F_ / 128, MAXROWS / 128), 256, SM_BYTES>>>(hidden, w1);
    mma_gemm<2><<<dim3(H_ / 128, MAXROWS / 128), 256, SM_BYTES>>>(nullptr, w2);
    combine_kernel<<<(T_ * H_ / 4) / 256, 256>>>(out);
    finalize_kernel<<<1, 32>>>(out);
}